// round 6
// baseline (speedup 1.0000x reference)
#include <cuda_runtime.h>
#include <cuda_fp16.h>
#include <cstdint>

// ---------------------------------------------------------------------------
// Fused LSTM cell, B=262144, I=H=C=O=128 (compute_100: mma.sync + cp.async).
// Kernel 1 (gates): persistent 148 CTAs x 512 thr, 1/SM. Col-half split:
//   CTA half=bi&1 holds 4 gates x 64 c-cols x 256 K fp16 = 128 KB RESIDENT
//   weights in smem. 64-row tiles, double-buffered A with register prefetch,
//   ONE __syncthreads per tile. Writes c,h (fp32) + h (fp16 scratch).
// Kernel 2 (y): 2048 CTAs x 256 thr, reads fp16 h scratch via cp.async,
//   w_out resident, writes y.
// out = [c | h | y] fp32.
// ---------------------------------------------------------------------------

#define HOFF 33554432L
#define YOFF 67108864L

// kernel1 smem (bytes)
#define SW1_B 0          // resident gate weight half: 131072
#define SA1_B 131072     // A double buffer: 2 x 32768
#define SB1_B 196608     // bias 4x128 fp32 = 2048
#define SMEM1 198656

// kernel2 smem
#define SH2_B 0          // h tile 128x128 fp16 = 32768
#define SO2_B 32768      // wout packed 32768
#define SMEM2 65536

// packed fp16 weights (filled by pack kernels every launch)
__device__ __align__(16) __half g_Wg[131072];     // gates, frag-linear
__device__ __align__(16) __half g_Wo[16384];      // wout, frag-linear
__device__ __align__(16) __half g_hbuf[33554432]; // h fp16 scratch [B,128]

__device__ __forceinline__ uint32_t smem_u32(const void* p) {
    uint32_t a;
    asm("{ .reg .u64 t; cvta.to.shared.u64 t, %1; cvt.u32.u64 %0, t; }" : "=r"(a) : "l"(p));
    return a;
}
__device__ __forceinline__ float tanhap(float x) {
    float y; asm("tanh.approx.f32 %0, %1;" : "=f"(y) : "f"(x)); return y;
}
__device__ __forceinline__ uint32_t packh2(float lo, float hi) {
    uint32_t r; asm("cvt.rn.f16x2.f32 %0, %1, %2;" : "=r"(r) : "f"(hi), "f"(lo));
    return r;
}
__device__ __forceinline__ void cpasync16(uint32_t s, const void* g) {
    asm volatile("cp.async.cg.shared.global [%0], [%1], 16;" :: "r"(s), "l"(g));
}
#define CP_COMMIT() asm volatile("cp.async.commit_group;" ::: "memory")
#define CP_WAIT0()  asm volatile("cp.async.wait_group 0;" ::: "memory")

__device__ __forceinline__ void mma16816(float* d,
                                         uint32_t a0, uint32_t a1, uint32_t a2, uint32_t a3,
                                         uint32_t b0, uint32_t b1) {
    asm volatile(
        "mma.sync.aligned.m16n8k16.row.col.f32.f16.f16.f32 "
        "{%0,%1,%2,%3}, {%4,%5,%6,%7}, {%8,%9}, {%0,%1,%2,%3};"
        : "+f"(d[0]), "+f"(d[1]), "+f"(d[2]), "+f"(d[3])
        : "r"(a0), "r"(a1), "r"(a2), "r"(a3), "r"(b0), "r"(b1));
}

// A-fragment load from XOR-swizzled smem (word idx = r*rw + (cw ^ 4*(r&7)))
__device__ __forceinline__ void lda(uint32_t* a, const uint32_t* base,
                                    int r, int kf, int lane, int rw) {
    int s = 4 * (r & 7);
    int c0 = kf * 8 + (lane & 3);
    a[0] = base[r * rw + (c0 ^ s)];
    a[1] = base[(r + 8) * rw + (c0 ^ s)];
    a[2] = base[r * rw + ((c0 + 4) ^ s)];
    a[3] = base[(r + 8) * rw + ((c0 + 4) ^ s)];
}

// ---------------------------------------------------------------------------
// Pack kernels: fp32 weights -> fragment-linear fp16.
// Gates word = ((((h*16+kf)*8 + wn)*4 + g)*32 + lane)*2 + reg
//   gate col gc = g*128+cc; h=cc>>6, wn=(cc>>3)&7, n=cc&7;
//   kf=k>>4, kk16=k&15, lane=n*4+((kk16>>1)&3), reg=kk16>>3.
// ---------------------------------------------------------------------------
__global__ void pack_gates(const float* __restrict__ w, const float* __restrict__ wi,
                           const float* __restrict__ wf, const float* __restrict__ wo) {
    int idx = blockIdx.x * 256 + threadIdx.x;        // 65536 words
    int gc = idx >> 7, k = (idx & 127) * 2;
    int g = gc >> 7, cc = gc & 127;
    const float* src = (g == 0) ? w : (g == 1) ? wi : (g == 2) ? wf : wo;
    float v0 = src[cc * 256 + k];
    float v1 = src[cc * 256 + k + 1];
    int h = cc >> 6, wn = (cc >> 3) & 7, n = cc & 7;
    int kf = k >> 4, kk16 = k & 15;
    int lane = n * 4 + ((kk16 >> 1) & 3), reg = kk16 >> 3;
    int word = ((((h * 16 + kf) * 8 + wn) * 4 + g) * 32 + lane) * 2 + reg;
    ((uint32_t*)g_Wg)[word] = packh2(v0, v1);
}

// Wout word = (((kf*4 + wn)*4 + jj)*32 + lane)*2 + reg;  yc = wn*32+jj*8+n.
__global__ void pack_wout(const float* __restrict__ w_out) {
    int idx = blockIdx.x * 256 + threadIdx.x;        // 8192 words
    int yc = idx >> 6, k = (idx & 63) * 2;
    float v0 = w_out[yc * 128 + k];
    float v1 = w_out[yc * 128 + k + 1];
    int wn = yc >> 5, jj = (yc >> 3) & 3, n = yc & 7;
    int kf = k >> 4, kk16 = k & 15;
    int lane = n * 4 + ((kk16 >> 1) & 3), reg = kk16 >> 3;
    int word = (((kf * 4 + wn) * 4 + jj) * 32 + lane) * 2 + reg;
    ((uint32_t*)g_Wo)[word] = packh2(v0, v1);
}

// ---------------------------------------------------------------------------
// Kernel 1: gates + c,h
// ---------------------------------------------------------------------------
__global__ void __launch_bounds__(512, 1)
lstm1(const float* __restrict__ c_, const float* __restrict__ h_,
      const float* __restrict__ x,
      const float* __restrict__ b, const float* __restrict__ bi,
      const float* __restrict__ bf, const float* __restrict__ bo,
      float* __restrict__ out) {
    extern __shared__ char smem[];
    const int tid = threadIdx.x;
    const int wid = tid >> 5;
    const int lane = tid & 31;
    const int wm = wid >> 3;               // 0..1: m-group (rows wm*32..+31)
    const int wn = wid & 7;                // 0..7: 8 c-cols x 4 gates
    const int half = blockIdx.x & 1;       // col half
    const int cid = blockIdx.x >> 1;       // 0..73

    const uint32_t* SWw = (const uint32_t*)(smem + SW1_B);
    uint32_t* SAw = (uint32_t*)(smem + SA1_B);
    float* sb = (float*)(smem + SB1_B);

    // resident weight half -> smem (once)
    {
        const char* src = (const char*)g_Wg + (size_t)half * 131072 + tid * 256;
        uint32_t dst = smem_u32(smem) + SW1_B + tid * 256;
#pragma unroll
        for (int i = 0; i < 16; i++) cpasync16(dst + i * 16, src + i * 16);
        CP_COMMIT();
    }
    if (tid < 128) {
        sb[tid]       = b[tid];
        sb[128 + tid] = bi[tid];
        sb[256 + tid] = bf[tid];
        sb[384 + tid] = bo[tid];
    }
    CP_WAIT0();
    __syncthreads();

    // A-fill role
    const int fr = tid >> 3;               // row 0..63
    const int fq = tid & 7;                // col chunk
    const float* psrc = (fq < 4) ? x : h_;
    const int pcol = (fq & 3) * 32;
    const int fs = 4 * (fr & 7);

    // epilogue / frag constants
    const int rb = wm * 32 + (lane >> 2);
    const int cpart = (lane & 3) * 2;
    const int cc0 = half * 64 + wn * 8 + cpart;

    // prefetch first tile
    float4 P[8];
    {
        const float* sp = psrc + ((long)cid * 64 + fr) * 128 + pcol;
#pragma unroll
        for (int i = 0; i < 8; i++) P[i] = *(const float4*)(sp + i * 4);
    }

    int buf = 0;
    for (int t = cid; t < 4096; t += 74) {
        // ---- STS A (current tile) from prefetch regs ----
        {
            uint32_t* dst = SAw + buf * 8192 + fr * 128;
#pragma unroll
            for (int i = 0; i < 8; i++) {
                int cw = fq * 16 + i * 2;
                *(uint2*)(dst + (cw ^ fs)) =
                    make_uint2(packh2(P[i].x, P[i].y), packh2(P[i].z, P[i].w));
            }
        }
        // ---- prefetch next tile's A source ----
        {
            int tn = (t + 74 < 4096) ? t + 74 : t;
            const float* sp = psrc + ((long)tn * 64 + fr) * 128 + pcol;
#pragma unroll
            for (int i = 0; i < 8; i++) P[i] = *(const float4*)(sp + i * 4);
        }
        __syncthreads();

        // ---- compute ----
        const long rowbase = (long)t * 64;
        float2 cin[2][2];
#pragma unroll
        for (int mf = 0; mf < 2; mf++)
#pragma unroll
            for (int rh = 0; rh < 2; rh++) {
                long gr = rowbase + rb + mf * 16 + rh * 8;
                cin[mf][rh] = *(const float2*)(c_ + gr * 128 + cc0);
            }

        float acc[2][4][4];
#pragma unroll
        for (int mf = 0; mf < 2; mf++)
#pragma unroll
            for (int g = 0; g < 4; g++)
#pragma unroll
                for (int q = 0; q < 4; q++) acc[mf][g][q] = 0.0f;

        const uint32_t* SA = SAw + buf * 8192;
#pragma unroll
        for (int kf = 0; kf < 16; kf++) {
            uint32_t a0[4], a1[4];
            lda(a0, SA, rb, kf, lane, 128);
            lda(a1, SA, rb + 16, kf, lane, 128);
#pragma unroll
            for (int g = 0; g < 4; g++) {
                const uint32_t* bp = SWw + ((kf * 8 + wn) * 4 + g) * 64 + lane * 2;
                uint32_t b0 = bp[0], b1 = bp[1];
                mma16816(acc[0][g], a0[0], a0[1], a0[2], a0[3], b0, b1);
                mma16816(acc[1][g], a1[0], a1[1], a1[2], a1[3], b0, b1);
            }
        }

        // ---- epilogue ----
#pragma unroll
        for (int mf = 0; mf < 2; mf++)
#pragma unroll
            for (int rh = 0; rh < 2; rh++) {
                const long gr = rowbase + rb + mf * 16 + rh * 8;
                float gz0 = acc[mf][0][rh * 2]     + sb[cc0];
                float gz1 = acc[mf][0][rh * 2 + 1] + sb[cc0 + 1];
                float gi0 = acc[mf][1][rh * 2]     + sb[128 + cc0];
                float gi1 = acc[mf][1][rh * 2 + 1] + sb[128 + cc0 + 1];
                float gf0 = acc[mf][2][rh * 2]     + sb[256 + cc0];
                float gf1 = acc[mf][2][rh * 2 + 1] + sb[256 + cc0 + 1];
                float go0 = acc[mf][3][rh * 2]     + sb[384 + cc0];
                float go1 = acc[mf][3][rh * 2 + 1] + sb[384 + cc0 + 1];
                float z0 = tanhap(gz0), z1 = tanhap(gz1);
                float si0 = 0.5f * tanhap(0.5f * gi0) + 0.5f;
                float si1 = 0.5f * tanhap(0.5f * gi1) + 0.5f;
                float sf0 = 0.5f * tanhap(0.5f * gf0) + 0.5f;
                float sf1 = 0.5f * tanhap(0.5f * gf1) + 0.5f;
                float so0 = 0.5f * tanhap(0.5f * go0) + 0.5f;
                float so1 = 0.5f * tanhap(0.5f * go1) + 0.5f;
                float c0 = sf0 * cin[mf][rh].x + si0 * z0;
                float c1 = sf1 * cin[mf][rh].y + si1 * z1;
                float h0 = so0 * tanhap(c0);
                float h1 = so1 * tanhap(c1);
                *(float2*)(out + gr * 128 + cc0) = make_float2(c0, c1);
                *(float2*)(out + HOFF + gr * 128 + cc0) = make_float2(h0, h1);
                ((uint32_t*)g_hbuf)[gr * 64 + (cc0 >> 1)] = packh2(h0, h1);
            }
        buf ^= 1;
    }
}

// ---------------------------------------------------------------------------
// Kernel 2: y = sigmoid(h @ wout^T + b_out)
// ---------------------------------------------------------------------------
__global__ void __launch_bounds__(256, 2)
lstm2(const float* __restrict__ b_out, float* __restrict__ out) {
    extern __shared__ char smem[];
    const int tid = threadIdx.x;
    const int wid = tid >> 5;
    const int lane = tid & 31;
    const int wm = wid >> 2;               // 0..1 (rows wm*64..+63)
    const int wn = wid & 3;                // 0..3 (ycols wn*32..+31)
    const long rowbase = (long)blockIdx.x * 128;

    const uint32_t* SH = (const uint32_t*)(smem + SH2_B);
    const uint32_t* SO = (const uint32_t*)(smem + SO2_B);

    // cp.async: h tile (swizzled dst) + wout (linear)
    {
        const int r = tid >> 1;            // 0..127
        const int hf = tid & 1;
        const char* src = (const char*)g_hbuf + (rowbase + r) * 256 + hf * 128;
        uint32_t dstb = smem_u32(smem) + SH2_B;
        const int s = 4 * (r & 7);
#pragma unroll
        for (int i = 0; i < 8; i++) {
            int cw = hf * 32 + i * 4;
            cpasync16(dstb + (r * 64 + (cw ^ s)) * 4, src + i * 16);
        }
        const char* wsrc = (const char*)g_Wo + tid * 128;
        uint32_t wdst = smem_u32(smem) + SO2_B + tid * 128;
#pragma unroll
        for (int i = 0; i < 8; i++) cpasync16(wdst + i * 16, wsrc + i * 16);
        CP_COMMIT();
    }

    const int rb = wm * 64 + (lane >> 2);
    const int cpart = (lane & 3) * 2;

    float2 bo2[4];
#pragma unroll
    for (int jj = 0; jj < 4; jj++)
        bo2[jj] = *(const float2*)(b_out + wn * 32 + jj * 8 + cpart);

    CP_WAIT0();
    __syncthreads();

    float acc[4][4][4];
#pragma unroll
    for (int mf = 0; mf < 4; mf++)
#pragma unroll
        for (int jj = 0; jj < 4; jj++)
#pragma unroll
            for (int q = 0; q < 4; q++) acc[mf][jj][q] = 0.0f;

#pragma unroll
    for (int kf = 0; kf < 8; kf++) {
        uint32_t a[4][4];
#pragma unroll
        for (int mf = 0; mf < 4; mf++)
            lda(a[mf], SH, rb + mf * 16, kf, lane, 64);
#pragma unroll
        for (int jj = 0; jj < 4; jj++) {
            const uint32_t* bp = SO + ((kf * 4 + wn) * 4 + jj) * 64 + lane * 2;
            uint32_t b0 = bp[0], b1 = bp[1];
#pragma unroll
            for (int mf = 0; mf < 4; mf++)
                mma16816(acc[mf][jj], a[mf][0], a[mf][1], a[mf][2], a[mf][3], b0, b1);
        }
    }

#pragma unroll
    for (int mf = 0; mf < 4; mf++)
#pragma unroll
        for (int rh = 0; rh < 2; rh++)
#pragma unroll
            for (int jj = 0; jj < 4; jj++) {
                const long gr = rowbase + rb + mf * 16 + rh * 8;
                const int yc = wn * 32 + jj * 8 + cpart;
                float v0 = acc[mf][jj][rh * 2]     + bo2[jj].x;
                float v1 = acc[mf][jj][rh * 2 + 1] + bo2[jj].y;
                float y0 = 0.5f * tanhap(0.5f * v0) + 0.5f;
                float y1 = 0.5f * tanhap(0.5f * v1) + 0.5f;
                *(float2*)(out + YOFF + gr * 128 + yc) = make_float2(y0, y1);
            }
}

extern "C" void kernel_launch(void* const* d_in, const int* in_sizes, int n_in,
                              void* d_out, int out_size) {
    const float* c_    = (const float*)d_in[0];
    const float* h_    = (const float*)d_in[1];
    const float* x     = (const float*)d_in[2];
    const float* w     = (const float*)d_in[3];
    const float* wi    = (const float*)d_in[4];
    const float* wf    = (const float*)d_in[5];
    const float* wo    = (const float*)d_in[6];
    const float* w_out = (const float*)d_in[7];
    const float* b     = (const float*)d_in[8];
    const float* bi    = (const float*)d_in[9];
    const float* bf    = (const float*)d_in[10];
    const float* bo    = (const float*)d_in[11];
    const float* b_out = (const float*)d_in[12];
    float* out = (float*)d_out;

    pack_gates<<<256, 256>>>(w, wi, wf, wo);
    pack_wout<<<32, 256>>>(w_out);
    cudaFuncSetAttribute(lstm1, cudaFuncAttributeMaxDynamicSharedMemorySize, SMEM1);
    cudaFuncSetAttribute(lstm2, cudaFuncAttributeMaxDynamicSharedMemorySize, SMEM2);
    lstm1<<<148, 512, SMEM1>>>(c_, h_, x, b, bi, bf, bo, out);
    lstm2<<<2048, 256, SMEM2>>>(b_out, out);
}

// round 7
// speedup vs baseline: 1.1618x; 1.1618x over previous
#include <cuda_runtime.h>
#include <cuda_fp16.h>
#include <cstdint>

// ---------------------------------------------------------------------------
// Fused LSTM cell, B=262144, I=H=C=O=128 (compute_100: mma.sync + cp.async).
// 2 CTAs/SM x 256 threads, 64-row tiles. 8 warps, each owns ALL 64 rows and
// an 8-c-col slice of all 4 gates. Weights streamed warp-privately through a
// TRIPLE-buffered cp.async pipeline (2 chunks always in flight). c_ loads
// issued a full MMA-phase early. Streaming cache hints on all bulk I/O.
// out = [c | h | y] fp32.
// ---------------------------------------------------------------------------

#define GRID   296
#define NT     4096          // 262144 / 64
#define HOFF   33554432L
#define YOFF   67108864L

// smem (bytes)
#define SA_B 0               // A tile: 64 x 256 half = 32768
#define SW_B 32768           // weight triple buffer: 3 x 16384 = 49152
#define SH_B 81920           // h tile: 64 x 128 half = 16384
#define SB_B 98304           // 640 floats = 2560
#define SMEM_TOTAL 100864

// packed fp16 weights, warp-slice linear (filled by pack kernels)
__device__ __align__(16) __half g_Wg[131072];   // gates 512x256
__device__ __align__(16) __half g_Wo[16384];    // wout 128x128

__device__ __forceinline__ uint32_t smem_u32(const void* p) {
    uint32_t a;
    asm("{ .reg .u64 t; cvta.to.shared.u64 t, %1; cvt.u32.u64 %0, t; }" : "=r"(a) : "l"(p));
    return a;
}
__device__ __forceinline__ float tanhap(float x) {
    float y; asm("tanh.approx.f32 %0, %1;" : "=f"(y) : "f"(x)); return y;
}
__device__ __forceinline__ uint32_t packh2(float lo, float hi) {
    uint32_t r; asm("cvt.rn.f16x2.f32 %0, %1, %2;" : "=r"(r) : "f"(hi), "f"(lo));
    return r;
}
__device__ __forceinline__ void cpasync16(uint32_t s, const void* g) {
    asm volatile("cp.async.cg.shared.global [%0], [%1], 16;" :: "r"(s), "l"(g));
}
#define CP_COMMIT() asm volatile("cp.async.commit_group;" ::: "memory")
#define CP_WAIT2()  asm volatile("cp.async.wait_group 2;" ::: "memory")
#define CP_WAIT1()  asm volatile("cp.async.wait_group 1;" ::: "memory")
#define CP_WAIT0()  asm volatile("cp.async.wait_group 0;" ::: "memory")

// streaming loads / stores
__device__ __forceinline__ float4 ldcs4(const float* p) {
    float4 v;
    asm volatile("ld.global.cs.v4.f32 {%0,%1,%2,%3}, [%4];"
                 : "=f"(v.x), "=f"(v.y), "=f"(v.z), "=f"(v.w) : "l"(p));
    return v;
}
__device__ __forceinline__ float2 ldcs2(const float* p) {
    float2 v;
    asm volatile("ld.global.cs.v2.f32 {%0,%1}, [%2];" : "=f"(v.x), "=f"(v.y) : "l"(p));
    return v;
}
__device__ __forceinline__ void stcs2(float* p, float a, float b) {
    asm volatile("st.global.cs.v2.f32 [%0], {%1,%2};" :: "l"(p), "f"(a), "f"(b));
}

__device__ __forceinline__ void mma16816(float* d,
                                         uint32_t a0, uint32_t a1, uint32_t a2, uint32_t a3,
                                         uint32_t b0, uint32_t b1) {
    asm volatile(
        "mma.sync.aligned.m16n8k16.row.col.f32.f16.f16.f32 "
        "{%0,%1,%2,%3}, {%4,%5,%6,%7}, {%8,%9}, {%0,%1,%2,%3};"
        : "+f"(d[0]), "+f"(d[1]), "+f"(d[2]), "+f"(d[3])
        : "r"(a0), "r"(a1), "r"(a2), "r"(a3), "r"(b0), "r"(b1));
}

// A-fragment load from XOR-swizzled smem (word idx = r*rw + (cw ^ 4*(r&7)))
__device__ __forceinline__ void lda(uint32_t* a, const uint32_t* base,
                                    int r, int kf, int lane, int rw) {
    int s = 4 * (r & 7);
    int c0 = kf * 8 + (lane & 3);
    a[0] = base[r * rw + (c0 ^ s)];
    a[1] = base[(r + 8) * rw + (c0 ^ s)];
    a[2] = base[r * rw + ((c0 + 4) ^ s)];
    a[3] = base[(r + 8) * rw + ((c0 + 4) ^ s)];
}

// ---------------------------------------------------------------------------
// Pack kernels (layouts identical to R5 — verified passing).
// ---------------------------------------------------------------------------
__global__ void pack_gates(const float* __restrict__ w, const float* __restrict__ wi,
                           const float* __restrict__ wf, const float* __restrict__ wo) {
    int idx = blockIdx.x * 256 + threadIdx.x;        // 65536 words
    int gc = idx >> 7, k = (idx & 127) * 2;
    int g = gc >> 7, cc = gc & 127;
    const float* src = (g == 0) ? w : (g == 1) ? wi : (g == 2) ? wf : wo;
    float v0 = src[cc * 256 + k];
    float v1 = src[cc * 256 + k + 1];
    int p = cc >> 6, wn = (cc >> 3) & 7, n = cc & 7;
    int ch = k >> 5, kk = (k >> 4) & 1, kk16 = k & 15;
    int lane = n * 4 + ((kk16 >> 1) & 3), reg = kk16 >> 3;
    int word = ((((p * 8 + ch) * 8 + wn) * 8 + kk * 4 + g) * 32 + lane) * 2 + reg;
    ((uint32_t*)g_Wg)[word] = packh2(v0, v1);
}

__global__ void pack_wout(const float* __restrict__ w_out) {
    int idx = blockIdx.x * 256 + threadIdx.x;        // 8192 words
    int yc = idx >> 6, k = (idx & 63) * 2;
    float v0 = w_out[yc * 128 + k];
    float v1 = w_out[yc * 128 + k + 1];
    int wn = yc >> 4, jj = (yc >> 3) & 1, n = yc & 7;
    int kf = k >> 4, ch = kf >> 2, kf4 = kf & 3, kk16 = k & 15;
    int lane = n * 4 + ((kk16 >> 1) & 3), reg = kk16 >> 3;
    int word = (((ch * 8 + wn) * 8 + kf4 * 2 + jj) * 32 + lane) * 2 + reg;
    ((uint32_t*)g_Wo)[word] = packh2(v0, v1);
}

// issue one warp-slice (2 KB) of global chunk s into triple buffer slot s%3
__device__ __forceinline__ void issue_chunk(int s, uint32_t sw_u32, int wn, int lane) {
    const char* src = (s < 16)
        ? (const char*)g_Wg + (size_t)s * 16384
        : (const char*)g_Wo + (size_t)(s - 16) * 16384;
    src += wn * 2048 + lane * 16;
    uint32_t dst = sw_u32 + (s % 3) * 16384 + wn * 2048 + lane * 16;
#pragma unroll
    for (int i = 0; i < 4; i++) cpasync16(dst + i * 512, src + i * 512);
    CP_COMMIT();
}

// ---------------------------------------------------------------------------
// Main persistent kernel
// ---------------------------------------------------------------------------
__global__ void __launch_bounds__(256, 2)
lstm_kernel(const float* __restrict__ c_, const float* __restrict__ h_,
            const float* __restrict__ x,
            const float* __restrict__ b, const float* __restrict__ bi,
            const float* __restrict__ bf, const float* __restrict__ bo,
            const float* __restrict__ b_out, float* __restrict__ out) {
    extern __shared__ char smem[];
    const int tid = threadIdx.x;
    const int wn = tid >> 5;             // warp 0..7 = n-slice
    const int lane = tid & 31;

    uint32_t* SAw = (uint32_t*)(smem + SA_B);
    uint32_t* SWw = (uint32_t*)(smem + SW_B);
    uint32_t* SHw = (uint32_t*)(smem + SH_B);
    float* sb = (float*)(smem + SB_B);
    const uint32_t sw_u32 = smem_u32(smem + SW_B);

    if (tid < 128) {
        sb[tid]       = b[tid];
        sb[128 + tid] = bi[tid];
        sb[256 + tid] = bf[tid];
        sb[384 + tid] = bo[tid];
        sb[512 + tid] = b_out[tid];
    }
    __syncthreads();

    const int rb0 = lane >> 2;           // fragment base row (0..7)
    const int cpart = (lane & 3) * 2;    // col pair within 8-col n-frag

    // prologue: start streaming chunks 0,1 of the first tile
    issue_chunk(0, sw_u32, wn, lane);
    issue_chunk(1, sw_u32, wn, lane);

    for (int t = blockIdx.x; t < NT; t += GRID) {
        const long rowbase = (long)t * 64;

        // ---- fill A = [x | h_] fp16, swizzled; 64 rows x 256 halfs ----
        {
            const int r = tid >> 2;
            const int q = tid & 3;
            const float* src = (q < 2) ? x : h_;
            const float* srow = src + (rowbase + r) * 128 + (q & 1) * 64;
            const int s = 4 * (r & 7);
            uint32_t* dst = SAw + r * 128;
#pragma unroll
            for (int i = 0; i < 16; i++) {
                float4 v = ldcs4(srow + i * 4);
                int cw = q * 32 + i * 2;
                *(uint2*)(dst + (cw ^ s)) =
                    make_uint2(packh2(v.x, v.y), packh2(v.z, v.w));
            }
        }
        __syncthreads();   // (a) A ready; prev tile's readers already past (c)

        // ================= gates: 2 passes x 8 chunks, warp-paced =========
        for (int p = 0; p < 2; p++) {
            const int cc0 = p * 64 + wn * 8 + cpart;

            // issue c_ loads for this pass early (consumed after MMA chunks)
            float2 cin[2][2];
#pragma unroll
            for (int mf2 = 0; mf2 < 2; mf2++)
#pragma unroll
                for (int rh = 0; rh < 2; rh++) {
                    // covers mf = mf2 and mf2+2 below via two groups of rows
                    long gr = rowbase + rb0 + (mf2 * 2) * 16 + rh * 8;
                    cin[mf2][rh] = ldcs2(c_ + gr * 128 + cc0);
                }
            float2 cin2[2][2];
#pragma unroll
            for (int mf2 = 0; mf2 < 2; mf2++)
#pragma unroll
                for (int rh = 0; rh < 2; rh++) {
                    long gr = rowbase + rb0 + (mf2 * 2 + 1) * 16 + rh * 8;
                    cin2[mf2][rh] = ldcs2(c_ + gr * 128 + cc0);
                }

            float acc[4][4][4];
#pragma unroll
            for (int mf = 0; mf < 4; mf++)
#pragma unroll
                for (int g = 0; g < 4; g++)
#pragma unroll
                    for (int q = 0; q < 4; q++) acc[mf][g][q] = 0.0f;

            for (int ch = 0; ch < 8; ch++) {
                const int s = p * 8 + ch;
                issue_chunk(s + 2, sw_u32, wn, lane);   // s+2 <= 17
                CP_WAIT2();
                __syncwarp();
                const uint32_t* wb = SWw + (s % 3) * 4096 + wn * 512;
#pragma unroll
                for (int kk = 0; kk < 2; kk++) {
                    const int kf = ch * 2 + kk;
                    uint32_t a[4][4];
#pragma unroll
                    for (int mf = 0; mf < 4; mf++)
                        lda(a[mf], SAw, rb0 + mf * 16, kf, lane, 128);
#pragma unroll
                    for (int g = 0; g < 4; g++) {
                        const uint32_t* bp = wb + (kk * 4 + g) * 64 + lane * 2;
                        uint32_t b0 = bp[0], b1 = bp[1];
#pragma unroll
                        for (int mf = 0; mf < 4; mf++)
                            mma16816(acc[mf][g], a[mf][0], a[mf][1], a[mf][2], a[mf][3], b0, b1);
                    }
                }
            }

            // ---- gates epilogue for pass p (warp-local, no sync) ----
#pragma unroll
            for (int mf = 0; mf < 4; mf++)
#pragma unroll
                for (int rh = 0; rh < 2; rh++) {
                    const int rl = rb0 + mf * 16 + rh * 8;
                    const long gr = rowbase + rl;
                    float2 cv = (mf & 1) ? cin2[mf >> 1][rh] : cin[mf >> 1][rh];
                    float gz0 = acc[mf][0][rh * 2]     + sb[cc0];
                    float gz1 = acc[mf][0][rh * 2 + 1] + sb[cc0 + 1];
                    float gi0 = acc[mf][1][rh * 2]     + sb[128 + cc0];
                    float gi1 = acc[mf][1][rh * 2 + 1] + sb[128 + cc0 + 1];
                    float gf0 = acc[mf][2][rh * 2]     + sb[256 + cc0];
                    float gf1 = acc[mf][2][rh * 2 + 1] + sb[256 + cc0 + 1];
                    float go0 = acc[mf][3][rh * 2]     + sb[384 + cc0];
                    float go1 = acc[mf][3][rh * 2 + 1] + sb[384 + cc0 + 1];
                    float z0 = tanhap(gz0), z1 = tanhap(gz1);
                    float si0 = 0.5f * tanhap(0.5f * gi0) + 0.5f;
                    float si1 = 0.5f * tanhap(0.5f * gi1) + 0.5f;
                    float sf0 = 0.5f * tanhap(0.5f * gf0) + 0.5f;
                    float sf1 = 0.5f * tanhap(0.5f * gf1) + 0.5f;
                    float so0 = 0.5f * tanhap(0.5f * go0) + 0.5f;
                    float so1 = 0.5f * tanhap(0.5f * go1) + 0.5f;
                    float c0 = sf0 * cv.x + si0 * z0;
                    float c1 = sf1 * cv.y + si1 * z1;
                    float h0 = so0 * tanhap(c0);
                    float h1 = so1 * tanhap(c1);
                    stcs2(out + gr * 128 + cc0, c0, c1);
                    stcs2(out + HOFF + gr * 128 + cc0, h0, h1);
                    SHw[rl * 64 + ((cc0 >> 1) ^ (4 * (rl & 7)))] = packh2(h0, h1);
                }
        }
        __syncthreads();   // (b) h tile complete

        // ================= y = sig(h @ wout^T + b_out) =====================
        {
            float ay[4][2][4];
#pragma unroll
            for (int mf = 0; mf < 4; mf++)
#pragma unroll
                for (int jj = 0; jj < 2; jj++)
#pragma unroll
                    for (int q = 0; q < 4; q++) ay[mf][jj][q] = 0.0f;

            for (int ch = 0; ch < 2; ch++) {
                const int s = 16 + ch;
                if (ch == 0) { CP_WAIT1(); } else { CP_WAIT0(); }
                __syncwarp();
                const uint32_t* wb = SWw + (s % 3) * 4096 + wn * 512;
#pragma unroll
                for (int kf4 = 0; kf4 < 4; kf4++) {
                    const int kf = ch * 4 + kf4;
                    uint32_t a[4][4];
#pragma unroll
                    for (int mf = 0; mf < 4; mf++)
                        lda(a[mf], SHw, rb0 + mf * 16, kf, lane, 64);
#pragma unroll
                    for (int jj = 0; jj < 2; jj++) {
                        const uint32_t* bp = wb + (kf4 * 2 + jj) * 64 + lane * 2;
                        uint32_t b0 = bp[0], b1 = bp[1];
#pragma unroll
                        for (int mf = 0; mf < 4; mf++)
                            mma16816(ay[mf][jj], a[mf][0], a[mf][1], a[mf][2], a[mf][3], b0, b1);
                    }
                }
            }

            // issue next tile's first two weight chunks during y epilogue
            if (t + GRID < NT) {
                issue_chunk(0, sw_u32, wn, lane);
                issue_chunk(1, sw_u32, wn, lane);
            }

#pragma unroll
            for (int mf = 0; mf < 4; mf++)
#pragma unroll
                for (int rh = 0; rh < 2; rh++)
#pragma unroll
                    for (int jj = 0; jj < 2; jj++) {
                        const int rl = rb0 + mf * 16 + rh * 8;
                        const long gr = rowbase + rl;
                        const int yc0 = wn * 16 + jj * 8 + cpart;
                        float v0 = ay[mf][jj][rh * 2]     + sb[512 + yc0];
                        float v1 = ay[mf][jj][rh * 2 + 1] + sb[512 + yc0 + 1];
                        float y0 = 0.5f * tanhap(0.5f * v0) + 0.5f;
                        float y1 = 0.5f * tanhap(0.5f * v1) + 0.5f;
                        stcs2(out + YOFF + gr * 128 + yc0, y0, y1);
                    }
        }
        __syncthreads();   // (c) SHw / A / Wbuf free for next tile
    }
}

extern "C" void kernel_launch(void* const* d_in, const int* in_sizes, int n_in,
                              void* d_out, int out_size) {
    const float* c_    = (const float*)d_in[0];
    const float* h_    = (const float*)d_in[1];
    const float* x     = (const float*)d_in[2];
    const float* w     = (const float*)d_in[3];
    const float* wi    = (const float*)d_in[4];
    const float* wf    = (const float*)d_in[5];
    const float* wo    = (const float*)d_in[6];
    const float* w_out = (const float*)d_in[7];
    const float* b     = (const float*)d_in[8];
    const float* bi    = (const float*)d_in[9];
    const float* bf    = (const float*)d_in[10];
    const float* bo    = (const float*)d_in[11];
    const float* b_out = (const float*)d_in[12];
    float* out = (float*)d_out;

    pack_gates<<<256, 256>>>(w, wi, wf, wo);
    pack_wout<<<32, 256>>>(w_out);
    cudaFuncSetAttribute(lstm_kernel, cudaFuncAttributeMaxDynamicSharedMemorySize, SMEM_TOTAL);
    lstm_kernel<<<GRID, 256, SMEM_TOTAL>>>(c_, h_, x, b, bi, bf, bo, b_out, out);
}